// round 5
// baseline (speedup 1.0000x reference)
#include <cuda_runtime.h>
#include <math.h>

#define N_AA_C   300000
#define N_PROT_C 30000
#define D        128
#define DOUT     64
#define E_AP_MAX 300000
#define E_PP_MAX 960000
#define BATCH    16384
#define NEG      0.2f

// ---------------- device scratch (static; no runtime allocation) -------------
__device__ float g_xl_pp[N_PROT_C * D];   // 15.4 MB (L2-resident)
__device__ float g_xr_pp[BATCH * D];
__device__ float g_xr_ap[BATCH * D];
__device__ float g_hid[BATCH * D];
__device__ float g_accap[BATCH * D];      // AP aggregated x (input space)
__device__ float g_ppout[BATCH * D];      // PP branch output
__device__ float g_logits[E_AP_MAX];

__device__ int g_cnt_ap[BATCH];
__device__ int g_cnt_pp[BATCH];
__device__ int g_off_ap[BATCH + 1];
__device__ int g_off_pp[BATCH + 1];
__device__ int g_cur_ap[BATCH];
__device__ int g_cur_pp[BATCH];
__device__ int g_src_ap[E_AP_MAX];
__device__ int g_dst_ap[E_AP_MAX];
__device__ int g_src_pp[E_PP_MAX];

__device__ __forceinline__ float lrelu(float x) { return x > 0.f ? x : NEG * x; }

// packed f32x2 helpers (Blackwell FFMA2 — only reachable via PTX)
__device__ __forceinline__ unsigned long long splat2(float x) {
    unsigned long long d;
    asm("mov.b64 %0, {%1, %1};" : "=l"(d) : "r"(__float_as_uint(x)));
    return d;
}
__device__ __forceinline__ unsigned long long pack2(float lo, float hi) {
    unsigned long long d;
    asm("mov.b64 %0, {%1, %2};" : "=l"(d) : "r"(__float_as_uint(lo)), "r"(__float_as_uint(hi)));
    return d;
}
__device__ __forceinline__ float2 unpack2(unsigned long long u) {
    float2 f;
    asm("mov.b64 {%0, %1}, %2;" : "=f"(f.x), "=f"(f.y) : "l"(u));
    return f;
}
__device__ __forceinline__ unsigned long long ffma2(
    unsigned long long a, unsigned long long b, unsigned long long c) {
    unsigned long long d;
    asm("fma.rn.f32x2 %0, %1, %2, %3;" : "=l"(d) : "l"(a), "l"(b), "l"(c));
    return d;
}

// ---------------- fused preprocessing kernels --------------------------------
__global__ void zero2_kernel(int* a, int* b) {
    int i = blockIdx.x * blockDim.x + threadIdx.x;
    if (i < BATCH) a[i] = 0;
    else if (i < 2 * BATCH) b[i - BATCH] = 0;
}

__global__ void hist2_kernel(const int* __restrict__ ei_ap, int E_ap, int* __restrict__ cnt_ap,
                             const int* __restrict__ ei_pp, int E_pp, int* __restrict__ cnt_pp) {
    int i = blockIdx.x * blockDim.x + threadIdx.x;
    if (i < E_ap) {
        int d = ei_ap[E_ap + i];
        if (d < BATCH) atomicAdd(&cnt_ap[d], 1);
    } else if (i < E_ap + E_pp) {
        int j = i - E_ap;
        int d = ei_pp[E_pp + j];
        if (d < BATCH) atomicAdd(&cnt_pp[d], 1);
    }
}

__global__ void scan2_kernel(const int* __restrict__ cnt_ap, int* __restrict__ off_ap, int* __restrict__ cur_ap,
                             const int* __restrict__ cnt_pp, int* __restrict__ off_pp, int* __restrict__ cur_pp) {
    const int* cnt = blockIdx.x ? cnt_pp : cnt_ap;
    int* off = blockIdx.x ? off_pp : off_ap;
    int* cur = blockIdx.x ? cur_pp : cur_ap;
    __shared__ int s[1024];
    int t = threadIdx.x;
    int v[16];
    int run = 0;
#pragma unroll
    for (int i = 0; i < 16; i++) { v[i] = run; run += cnt[t * 16 + i]; }
    s[t] = run;
    __syncthreads();
    for (int d = 1; d < 1024; d <<= 1) {
        int add = (t >= d) ? s[t - d] : 0;
        __syncthreads();
        s[t] += add;
        __syncthreads();
    }
    int base = (t > 0) ? s[t - 1] : 0;
#pragma unroll
    for (int i = 0; i < 16; i++) {
        int o = base + v[i];
        off[t * 16 + i] = o;
        cur[t * 16 + i] = o;
    }
    if (t == 1023) off[16384] = s[1023];
}

__global__ void scatter2_kernel(const int* __restrict__ ei_ap, int E_ap, int* __restrict__ cur_ap,
                                int* __restrict__ src_ap, int* __restrict__ dst_ap,
                                const int* __restrict__ ei_pp, int E_pp, int* __restrict__ cur_pp,
                                int* __restrict__ src_pp) {
    int i = blockIdx.x * blockDim.x + threadIdx.x;
    if (i < E_ap) {
        int d = ei_ap[E_ap + i];
        if (d < BATCH) {
            int p = atomicAdd(&cur_ap[d], 1);
            src_ap[p] = ei_ap[i];
            dst_ap[p] = d;
        }
    } else if (i < E_ap + E_pp) {
        int j = i - E_ap;
        int d = ei_pp[E_pp + j];
        if (d < BATCH) {
            int p = atomicAdd(&cur_pp[d], 1);
            src_pp[p] = ei_pp[j];
        }
    }
}

// ---------------- 128x128-tile GEMM, k-chunked double-buffered ---------------
// 256 thr, 8x8 per-thread register block, K in 8 chunks of 16, 32 KB smem.
// MODE 0: Y = X @ W + bias1
// MODE 1: gather rows via srcs; per-row GATv2 logits only
// MODE 2: Y = X @ W + bias1 + bias2 + addmat
template <int MODE>
__global__ void __launch_bounds__(256) gemm_kernel(
    const float* __restrict__ X, const float* __restrict__ W,
    const float* __restrict__ bias1, const float* __restrict__ bias2,
    float* __restrict__ Y, int nrows_const,
    const int* __restrict__ srcs, const int* __restrict__ total_ptr,
    const int* __restrict__ dst_arr, const float* __restrict__ xr,
    const float* __restrict__ att, float* __restrict__ logits,
    const float* __restrict__ addmat) {
    int total = (MODE == 1) ? *total_ptr : nrows_const;
    int row0 = blockIdx.x * 128;
    if (row0 >= total) return;

    __shared__ float Ws[2][16][128];   // [buf][k-in-chunk][n]
    __shared__ float Xs[2][16][128];   // [buf][k-in-chunk][m] (transposed)

    int t = threadIdx.x;
    int tx = t & 15, ty = t >> 4;
    int tx8 = tx * 8, ty8 = ty * 8;

    // staging assignments
    int m_a = t >> 2, kq = t & 3;      // X: thread loads rows m_a and m_a+64, float4 col kq
    int m_b = m_a + 64;
    int kw_a = t >> 5, nw = t & 31;    // W: rows kw_a and kw_a+8 (in chunk), float4 col nw
    int kw_b = kw_a + 8;

    int ra = row0 + m_a, rb = row0 + m_b;
    int rra = (ra < total) ? ((MODE == 1) ? srcs[ra] : ra) : 0;
    int rrb = (rb < total) ? ((MODE == 1) ? srcs[rb] : rb) : 0;
    const float4* X4 = (const float4*)X;
    const float4* W4 = (const float4*)W;

    // accumulator init with bias (cols tx8..tx8+7)
    unsigned long long acc[8][4];
    {
        float4 q0 = ((const float4*)bias1)[tx * 2];
        float4 q1 = ((const float4*)bias1)[tx * 2 + 1];
        if (MODE == 2) {
            float4 p0 = ((const float4*)bias2)[tx * 2];
            float4 p1 = ((const float4*)bias2)[tx * 2 + 1];
            q0.x += p0.x; q0.y += p0.y; q0.z += p0.z; q0.w += p0.w;
            q1.x += p1.x; q1.y += p1.y; q1.z += p1.z; q1.w += p1.w;
        }
        unsigned long long i0 = pack2(q0.x, q0.y), i1 = pack2(q0.z, q0.w);
        unsigned long long i2 = pack2(q1.x, q1.y), i3 = pack2(q1.z, q1.w);
#pragma unroll
        for (int r = 0; r < 8; r++) { acc[r][0] = i0; acc[r][1] = i1; acc[r][2] = i2; acc[r][3] = i3; }
    }

    // prologue: stage chunk 0
    float4 xg_a = X4[(size_t)rra * 32 + kq];
    float4 xg_b = X4[(size_t)rrb * 32 + kq];
    float4 wg_a = W4[kw_a * 32 + nw];
    float4 wg_b = W4[kw_b * 32 + nw];
    {
        ((float4*)&Ws[0][kw_a][nw * 4])[0] = wg_a;
        ((float4*)&Ws[0][kw_b][nw * 4])[0] = wg_b;
        Xs[0][kq * 4 + 0][m_a] = xg_a.x; Xs[0][kq * 4 + 1][m_a] = xg_a.y;
        Xs[0][kq * 4 + 2][m_a] = xg_a.z; Xs[0][kq * 4 + 3][m_a] = xg_a.w;
        Xs[0][kq * 4 + 0][m_b] = xg_b.x; Xs[0][kq * 4 + 1][m_b] = xg_b.y;
        Xs[0][kq * 4 + 2][m_b] = xg_b.z; Xs[0][kq * 4 + 3][m_b] = xg_b.w;
    }
    __syncthreads();

#pragma unroll
    for (int c = 0; c < 8; c++) {
        int buf = c & 1;
        if (c < 7) {
            xg_a = X4[(size_t)rra * 32 + (c + 1) * 4 + kq];
            xg_b = X4[(size_t)rrb * 32 + (c + 1) * 4 + kq];
            wg_a = W4[((c + 1) * 16 + kw_a) * 32 + nw];
            wg_b = W4[((c + 1) * 16 + kw_b) * 32 + nw];
        }
#pragma unroll
        for (int kk = 0; kk < 16; kk++) {
            float4 a0 = *(const float4*)&Xs[buf][kk][ty8];
            float4 a1 = *(const float4*)&Xs[buf][kk][ty8 + 4];
            ulonglong2 b01 = *(const ulonglong2*)&Ws[buf][kk][tx8];
            ulonglong2 b23 = *(const ulonglong2*)&Ws[buf][kk][tx8 + 4];
            float av[8] = {a0.x, a0.y, a0.z, a0.w, a1.x, a1.y, a1.z, a1.w};
#pragma unroll
            for (int r = 0; r < 8; r++) {
                unsigned long long s = splat2(av[r]);
                acc[r][0] = ffma2(s, b01.x, acc[r][0]);
                acc[r][1] = ffma2(s, b01.y, acc[r][1]);
                acc[r][2] = ffma2(s, b23.x, acc[r][2]);
                acc[r][3] = ffma2(s, b23.y, acc[r][3]);
            }
        }
        if (c < 7) {
            int nb = buf ^ 1;
            ((float4*)&Ws[nb][kw_a][nw * 4])[0] = wg_a;
            ((float4*)&Ws[nb][kw_b][nw * 4])[0] = wg_b;
            Xs[nb][kq * 4 + 0][m_a] = xg_a.x; Xs[nb][kq * 4 + 1][m_a] = xg_a.y;
            Xs[nb][kq * 4 + 2][m_a] = xg_a.z; Xs[nb][kq * 4 + 3][m_a] = xg_a.w;
            Xs[nb][kq * 4 + 0][m_b] = xg_b.x; Xs[nb][kq * 4 + 1][m_b] = xg_b.y;
            Xs[nb][kq * 4 + 2][m_b] = xg_b.z; Xs[nb][kq * 4 + 3][m_b] = xg_b.w;
            __syncthreads();
        }
    }

    if (MODE == 1) {
        // GATv2 logit epilogue: p = sum_c att[c] * lrelu(xl[c] + xr[dst][c])
        float4 at0 = ((const float4*)att)[tx * 2];
        float4 at1 = ((const float4*)att)[tx * 2 + 1];
#pragma unroll
        for (int r = 0; r < 8; r++) {
            int row = row0 + ty8 + r;
            float p = 0.f;
            if (row < total) {
                int dd = dst_arr[row];
                float4 x0 = ((const float4*)xr)[(size_t)dd * 32 + tx * 2];
                float4 x1 = ((const float4*)xr)[(size_t)dd * 32 + tx * 2 + 1];
                float2 v0 = unpack2(acc[r][0]), v1 = unpack2(acc[r][1]);
                float2 v2 = unpack2(acc[r][2]), v3 = unpack2(acc[r][3]);
                p = at0.x * lrelu(v0.x + x0.x) + at0.y * lrelu(v0.y + x0.y)
                  + at0.z * lrelu(v1.x + x0.z) + at0.w * lrelu(v1.y + x0.w)
                  + at1.x * lrelu(v2.x + x1.x) + at1.y * lrelu(v2.y + x1.y)
                  + at1.z * lrelu(v3.x + x1.z) + at1.w * lrelu(v3.y + x1.w);
            }
#pragma unroll
            for (int o = 8; o; o >>= 1) p += __shfl_xor_sync(0xffffffffu, p, o);
            if (tx == 0 && row < total) logits[row] = p;
        }
    } else {
#pragma unroll
        for (int r = 0; r < 8; r++) {
            int row = row0 + ty8 + r;
            if (row < total) {
                float2 v0 = unpack2(acc[r][0]), v1 = unpack2(acc[r][1]);
                float2 v2 = unpack2(acc[r][2]), v3 = unpack2(acc[r][3]);
                float4 o0 = make_float4(v0.x, v0.y, v1.x, v1.y);
                float4 o1 = make_float4(v2.x, v2.y, v3.x, v3.y);
                if (MODE == 2) {
                    float4 m0 = ((const float4*)addmat)[(size_t)row * 32 + tx * 2];
                    float4 m1 = ((const float4*)addmat)[(size_t)row * 32 + tx * 2 + 1];
                    o0.x += m0.x; o0.y += m0.y; o0.z += m0.z; o0.w += m0.w;
                    o1.x += m1.x; o1.y += m1.y; o1.z += m1.z; o1.w += m1.w;
                }
                ((float4*)Y)[(size_t)row * 32 + tx * 2] = o0;
                ((float4*)Y)[(size_t)row * 32 + tx * 2 + 1] = o1;
            }
        }
    }
}

// ---------------- PP online segment softmax over gathered xl rows ------------
__device__ __forceinline__ float4 seg_softmax_pp(
    const float* __restrict__ xl, const int* __restrict__ srcs,
    int e0, int e1, float4 xrv, float4 attv, int lane) {
    float m = -INFINITY, denom = 0.f;
    float4 acc = make_float4(0.f, 0.f, 0.f, 0.f);

    for (int eb = e0; eb < e1; eb += 4) {
        int g = min(4, e1 - eb);
        int sl = (lane < g) ? srcs[eb + lane] : 0;
        float4 xv[4];
        float lg[4];
#pragma unroll
        for (int i = 0; i < 4; i++) {
            if (i < g) {
                int row = __shfl_sync(0xffffffffu, sl, i);
                xv[i] = ((const float4*)xl)[(size_t)row * 32 + lane];
            }
        }
#pragma unroll
        for (int i = 0; i < 4; i++) {
            if (i < g) {
                float p = lrelu(xv[i].x + xrv.x) * attv.x
                        + lrelu(xv[i].y + xrv.y) * attv.y
                        + lrelu(xv[i].z + xrv.z) * attv.z
                        + lrelu(xv[i].w + xrv.w) * attv.w;
#pragma unroll
                for (int o = 16; o; o >>= 1) p += __shfl_xor_sync(0xffffffffu, p, o);
                lg[i] = p;
            }
        }
        float gm = m;
#pragma unroll
        for (int i = 0; i < 4; i++) if (i < g) gm = fmaxf(gm, lg[i]);
        float sc = __expf(m - gm);
        denom *= sc; acc.x *= sc; acc.y *= sc; acc.z *= sc; acc.w *= sc;
#pragma unroll
        for (int i = 0; i < 4; i++) {
            if (i < g) {
                float w = __expf(lg[i] - gm);
                denom += w;
                acc.x += w * xv[i].x; acc.y += w * xv[i].y;
                acc.z += w * xv[i].z; acc.w += w * xv[i].w;
            }
        }
        m = gm;
    }
    float inv = (denom > 0.f) ? 1.f / denom : 0.f;
    acc.x *= inv; acc.y *= inv; acc.z *= inv; acc.w *= inv;
    return acc;
}

// warp per dst: AP (logit-based softmax over x_aa rows) + PP (online over xl_pp)
__global__ void __launch_bounds__(256) agg_kernel(
    const float* __restrict__ x_aa, const float* __restrict__ logits,
    const int* __restrict__ off_ap, const int* __restrict__ src_ap,
    const float* __restrict__ xl_pp, const float* __restrict__ xr_pp,
    const float* __restrict__ att_pp, const float* __restrict__ bias_pp,
    const int* __restrict__ off_pp, const int* __restrict__ src_pp,
    float* __restrict__ accap, float* __restrict__ pp_out) {
    int t = threadIdx.x, lane = t & 31, warp = t >> 5;
    int dst = blockIdx.x * 8 + warp;

    // ---- AP: softmax weights from precomputed logits, accumulate raw x rows
    int e0 = off_ap[dst], e1 = off_ap[dst + 1];
    float4 acc = make_float4(0.f, 0.f, 0.f, 0.f);
    if (e1 > e0) {
        float m = -INFINITY, denom = 0.f;
        for (int base = e0; base < e1; base += 32) {
            int e = base + lane;
            bool valid = (e < e1);
            float le = valid ? logits[e] : -INFINITY;
            float cm = le;
#pragma unroll
            for (int o = 16; o; o >>= 1) cm = fmaxf(cm, __shfl_xor_sync(0xffffffffu, cm, o));
            if (cm > m) { denom *= __expf(m - cm); m = cm; }
            float w = valid ? __expf(le - m) : 0.f;
#pragma unroll
            for (int o = 16; o; o >>= 1) w += __shfl_xor_sync(0xffffffffu, w, o);
            denom += w;
        }
        float inv = 1.f / denom;
        int e = e0;
        for (; e + 3 < e1; e += 4) {
            int s0 = src_ap[e], s1 = src_ap[e + 1], s2 = src_ap[e + 2], s3 = src_ap[e + 3];
            float4 x0 = ((const float4*)x_aa)[(size_t)s0 * 32 + lane];
            float4 x1 = ((const float4*)x_aa)[(size_t)s1 * 32 + lane];
            float4 x2 = ((const float4*)x_aa)[(size_t)s2 * 32 + lane];
            float4 x3 = ((const float4*)x_aa)[(size_t)s3 * 32 + lane];
            float al0 = __expf(logits[e] - m) * inv;
            float al1 = __expf(logits[e + 1] - m) * inv;
            float al2 = __expf(logits[e + 2] - m) * inv;
            float al3 = __expf(logits[e + 3] - m) * inv;
            acc.x += al0 * x0.x + al1 * x1.x + al2 * x2.x + al3 * x3.x;
            acc.y += al0 * x0.y + al1 * x1.y + al2 * x2.y + al3 * x3.y;
            acc.z += al0 * x0.z + al1 * x1.z + al2 * x2.z + al3 * x3.z;
            acc.w += al0 * x0.w + al1 * x1.w + al2 * x2.w + al3 * x3.w;
        }
        for (; e < e1; e++) {
            int s0 = src_ap[e];
            float al0 = __expf(logits[e] - m) * inv;
            float4 x0 = ((const float4*)x_aa)[(size_t)s0 * 32 + lane];
            acc.x += al0 * x0.x; acc.y += al0 * x0.y;
            acc.z += al0 * x0.z; acc.w += al0 * x0.w;
        }
    }
    ((float4*)accap)[(size_t)dst * 32 + lane] = acc;

    // ---- PP: online softmax over precomputed xl_pp rows (L2-resident)
    float4 attv = ((const float4*)att_pp)[lane];
    float4 bsv  = ((const float4*)bias_pp)[lane];
    float4 xrv  = ((const float4*)xr_pp)[(size_t)dst * 32 + lane];
    float4 pp = seg_softmax_pp(xl_pp, src_pp, off_pp[dst], off_pp[dst + 1], xrv, attv, lane);
    pp.x += bsv.x; pp.y += bsv.y; pp.z += bsv.z; pp.w += bsv.w;
    ((float4*)pp_out)[(size_t)dst * 32 + lane] = pp;
}

// ---------------- out = relu(hid) @ W_lin + b_lin  (128 -> 64) ---------------
__global__ void __launch_bounds__(256) final_kernel(
    const float* __restrict__ hid, const float* __restrict__ Wl,
    const float* __restrict__ bl, float* __restrict__ out) {
    extern __shared__ float sm[];
    float* Ws = sm;              // 128*64 = 32KB
    float* hs = sm + D * DOUT;   // 32*128 = 16KB
    int t = threadIdx.x, lane = t & 31, warp = t >> 5;

    for (int i = t; i < D * DOUT / 4; i += 256) ((float4*)Ws)[i] = ((const float4*)Wl)[i];

    int row0 = blockIdx.x * 32 + warp * 4;
#pragma unroll
    for (int r = 0; r < 4; r++) {
        float4 h = ((const float4*)hid)[(size_t)(row0 + r) * 32 + lane];
        h.x = fmaxf(h.x, 0.f); h.y = fmaxf(h.y, 0.f);
        h.z = fmaxf(h.z, 0.f); h.w = fmaxf(h.w, 0.f);
        ((float4*)&hs[(warp * 4 + r) * D])[lane] = h;
    }
    __syncthreads();

    float b0 = bl[lane], b1 = bl[lane + 32];
    float acc0[4], acc1[4];
#pragma unroll
    for (int r = 0; r < 4; r++) { acc0[r] = b0; acc1[r] = b1; }

    for (int k = 0; k < D; k++) {
        float w0 = Ws[k * DOUT + lane];
        float w1 = Ws[k * DOUT + lane + 32];
#pragma unroll
        for (int r = 0; r < 4; r++) {
            float h = hs[(warp * 4 + r) * D + k];
            acc0[r] += h * w0;
            acc1[r] += h * w1;
        }
    }
#pragma unroll
    for (int r = 0; r < 4; r++) {
        int row = row0 + r;
        out[(size_t)row * DOUT + lane] = acc0[r];
        out[(size_t)row * DOUT + lane + 32] = acc1[r];
    }
}

// ---------------- launch ------------------------------------------------------
extern "C" void kernel_launch(void* const* d_in, const int* in_sizes, int n_in,
                              void* d_out, int out_size) {
    const float* x_aa    = (const float*)d_in[0];
    const float* x_prot  = (const float*)d_in[1];
    const int*   ei_ap   = (const int*)d_in[2];
    const int*   ei_pp   = (const int*)d_in[3];
    const float* Wl_ap   = (const float*)d_in[5];
    const float* bl_ap   = (const float*)d_in[6];
    const float* Wr_ap   = (const float*)d_in[7];
    const float* br_ap   = (const float*)d_in[8];
    const float* att_ap  = (const float*)d_in[9];
    const float* bias_ap = (const float*)d_in[10];
    const float* Wl_pp   = (const float*)d_in[11];
    const float* bl_pp   = (const float*)d_in[12];
    const float* Wr_pp   = (const float*)d_in[13];
    const float* br_pp   = (const float*)d_in[14];
    const float* att_pp  = (const float*)d_in[15];
    const float* bias_pp = (const float*)d_in[16];
    const float* W_lin   = (const float*)d_in[17];
    const float* b_lin   = (const float*)d_in[18];
    float* out = (float*)d_out;

    int E_ap = in_sizes[2] / 2;
    int E_pp = in_sizes[3] / 2;

    void* p;
    cudaGetSymbolAddress(&p, g_xl_pp);  float* xl_pp  = (float*)p;
    cudaGetSymbolAddress(&p, g_xr_pp);  float* xr_pp  = (float*)p;
    cudaGetSymbolAddress(&p, g_xr_ap);  float* xr_ap  = (float*)p;
    cudaGetSymbolAddress(&p, g_hid);    float* hid    = (float*)p;
    cudaGetSymbolAddress(&p, g_accap);  float* accap  = (float*)p;
    cudaGetSymbolAddress(&p, g_ppout);  float* ppout  = (float*)p;
    cudaGetSymbolAddress(&p, g_logits); float* logits = (float*)p;
    cudaGetSymbolAddress(&p, g_cnt_ap); int* cnt_ap = (int*)p;
    cudaGetSymbolAddress(&p, g_cnt_pp); int* cnt_pp = (int*)p;
    cudaGetSymbolAddress(&p, g_off_ap); int* off_ap = (int*)p;
    cudaGetSymbolAddress(&p, g_off_pp); int* off_pp = (int*)p;
    cudaGetSymbolAddress(&p, g_cur_ap); int* cur_ap = (int*)p;
    cudaGetSymbolAddress(&p, g_cur_pp); int* cur_pp = (int*)p;
    cudaGetSymbolAddress(&p, g_src_ap); int* src_ap = (int*)p;
    cudaGetSymbolAddress(&p, g_dst_ap); int* dst_ap = (int*)p;
    cudaGetSymbolAddress(&p, g_src_pp); int* src_pp = (int*)p;

    cudaFuncSetAttribute(final_kernel, cudaFuncAttributeMaxDynamicSharedMemorySize, 49152);

    int E_both = E_ap + E_pp;

    // 0-2: preprocessing front half
    zero2_kernel<<<(2 * BATCH + 255) / 256, 256>>>(cnt_ap, cnt_pp);
    hist2_kernel<<<(E_both + 255) / 256, 256>>>(ei_ap, E_ap, cnt_ap, ei_pp, E_pp, cnt_pp);
    scan2_kernel<<<2, 1024>>>(cnt_ap, off_ap, cur_ap, cnt_pp, off_pp, cur_pp);
    // 3 (ncu slot): xl_pp = x_prot @ Wl_pp + bl_pp — A/B vs round 2's 42.4us
    gemm_kernel<0><<<(N_PROT_C + 127) / 128, 256>>>(
        x_prot, Wl_pp, bl_pp, nullptr, xl_pp, N_PROT_C,
        nullptr, nullptr, nullptr, nullptr, nullptr, nullptr, nullptr);
    // 4: scatter src indices into dst-sorted order
    scatter2_kernel<<<(E_both + 255) / 256, 256>>>(ei_ap, E_ap, cur_ap, src_ap, dst_ap,
                                                   ei_pp, E_pp, cur_pp, src_pp);
    // 5: xr_ap = x_prot @ Wr_ap + br_ap (needed by edge-GEMM logit epilogue)
    gemm_kernel<0><<<BATCH / 128, 256>>>(
        x_prot, Wr_ap, br_ap, nullptr, xr_ap, BATCH,
        nullptr, nullptr, nullptr, nullptr, nullptr, nullptr, nullptr);
    // 6: AP edge GEMM -> logits only
    gemm_kernel<1><<<(E_AP_MAX + 127) / 128, 256>>>(
        x_aa, Wl_ap, bl_ap, nullptr, nullptr, 0,
        src_ap, &off_ap[BATCH], dst_ap, xr_ap, att_ap, logits, nullptr);
    // 7: xr_pp
    gemm_kernel<0><<<BATCH / 128, 256>>>(
        x_prot, Wr_pp, br_pp, nullptr, xr_pp, BATCH,
        nullptr, nullptr, nullptr, nullptr, nullptr, nullptr, nullptr);
    // 8: fused AP (logit softmax over x_aa) + PP (online over xl_pp) aggregation
    agg_kernel<<<BATCH / 8, 256>>>(x_aa, logits, off_ap, src_ap,
                                   xl_pp, xr_pp, att_pp, bias_pp, off_pp, src_pp,
                                   accap, ppout);
    // 9: hid = accap @ Wl_ap + bl_ap + bias_ap + ppout
    gemm_kernel<2><<<BATCH / 128, 256>>>(
        accap, Wl_ap, bl_ap, bias_ap, hid, BATCH,
        nullptr, nullptr, nullptr, nullptr, nullptr, nullptr, ppout);
    // 10: relu + final linear
    final_kernel<<<BATCH / 32, 256, 49152>>>(hid, W_lin, b_lin, out);
}

// round 10
// speedup vs baseline: 1.0743x; 1.0743x over previous
#include <cuda_runtime.h>
#include <cuda_bf16.h>
#include <stdint.h>
#include <math.h>
#define D 128
#define DOUT 64
#define NP 30000
#define EA 300000
#define EP 960000
#define B 16384
#define NEG 0.2f
typedef unsigned long long u64;
typedef unsigned int u32;

__device__ float g_xlpp[NP*D];
__device__ float g_xrpp[B*D];
__device__ float g_xrap[B*D];
__device__ float g_hid[B*D];
__device__ float g_acc[B*D];
__device__ float g_ppo[B*D];
__device__ float g_lg[EA];
__device__ u32 g_Bh[8448];   // Wl_ap^T bf16-hi, [n=128][k padded to 132]
__device__ u32 g_Bl[8448];   // bf16-lo residual
__device__ int g_ca[B], g_cp[B], g_oa[B+1], g_op[B+1], g_ua[B], g_up[B];
__device__ int g_sa[EA], g_da[EA], g_sp[EP];

__device__ __forceinline__ float lrelu(float x){ return x>0.f?x:NEG*x; }
__device__ __forceinline__ u64 splat2(float x){ u64 d; asm("mov.b64 %0,{%1,%1};":"=l"(d):"r"(__float_as_uint(x))); return d; }
__device__ __forceinline__ u64 pack2(float a,float b){ u64 d; asm("mov.b64 %0,{%1,%2};":"=l"(d):"r"(__float_as_uint(a)),"r"(__float_as_uint(b))); return d; }
__device__ __forceinline__ float2 unpack2(u64 u){ float2 f; asm("mov.b64 {%0,%1},%2;":"=f"(f.x),"=f"(f.y):"l"(u)); return f; }
__device__ __forceinline__ u64 ffma2(u64 a,u64 b,u64 c){ u64 d; asm("fma.rn.f32x2 %0,%1,%2,%3;":"=l"(d):"l"(a),"l"(b),"l"(c)); return d; }
__device__ __forceinline__ u32 cbf2(float lo,float hi){ u32 r; asm("cvt.rn.bf16x2.f32 %0,%1,%2;":"=r"(r):"f"(hi),"f"(lo)); return r; }
__device__ __forceinline__ float blo(u32 r){ return __uint_as_float(r<<16); }
__device__ __forceinline__ float bhi(u32 r){ return __uint_as_float(r&0xffff0000u); }
// HMMA m16n8k16 bf16 -> f32 (sm_80+ PTX, compiles for compute_103)
__device__ __forceinline__ void mmab(float* c,u32 a0,u32 a1,u32 a2,u32 a3,u32 b0,u32 b1){
    asm volatile("mma.sync.aligned.m16n8k16.row.col.f32.bf16.bf16.f32 "
        "{%0,%1,%2,%3},{%4,%5,%6,%7},{%8,%9},{%0,%1,%2,%3};"
        :"+f"(c[0]),"+f"(c[1]),"+f"(c[2]),"+f"(c[3])
        :"r"(a0),"r"(a1),"r"(a2),"r"(a3),"r"(b0),"r"(b1));
}

// zero histograms + prep B images (Wla [k][n] -> [n][132] bf16 hi/lo) in one launch
__global__ void k_zero(int* a,int* b,const float* W,u32* ih,u32* il){
    int i=blockIdx.x*blockDim.x+threadIdx.x;
    if(i<B) a[i]=0;
    else if(i<2*B) b[i-B]=0;
    else if(i<2*B+16384){
        int idx=i-2*B;
        int k=idx>>7,n=idx&127;
        float v=W[idx];
        __nv_bfloat16 h=__float2bfloat16(v);
        __nv_bfloat16 l=__float2bfloat16(v-__bfloat162float(h));
        ((__nv_bfloat16*)ih)[n*132+k]=h;
        ((__nv_bfloat16*)il)[n*132+k]=l;
    }
}
__global__ void k_hist(const int* ea,int Ea,int* ca,const int* ep,int Ep,int* cp){
    int i=blockIdx.x*blockDim.x+threadIdx.x;
    if(i<Ea){ int d=ea[Ea+i]; if(d<B) atomicAdd(&ca[d],1); }
    else if(i<Ea+Ep){ int d=ep[Ep+i-Ea]; if(d<B) atomicAdd(&cp[d],1); }
}
__global__ void k_scan(const int* ca,int* oa,int* ua,const int* cp,int* op,int* up){
    const int* cnt=blockIdx.x?cp:ca;
    int* off=blockIdx.x?op:oa;
    int* cur=blockIdx.x?up:ua;
    __shared__ int s[1024];
    int t=threadIdx.x,v[16],run=0;
#pragma unroll
    for(int i=0;i<16;i++){ v[i]=run; run+=cnt[t*16+i]; }
    s[t]=run; __syncthreads();
    for(int d=1;d<1024;d<<=1){
        int add=(t>=d)?s[t-d]:0; __syncthreads();
        s[t]+=add; __syncthreads();
    }
    int base=(t>0)?s[t-1]:0;
#pragma unroll
    for(int i=0;i<16;i++){ int o=base+v[i]; off[t*16+i]=o; cur[t*16+i]=o; }
    if(t==1023) off[16384]=s[1023];
}
__global__ void k_scat(const int* ea,int Ea,int* ua,int* sa,int* da,const int* ep,int Ep,int* up,int* sp){
    int i=blockIdx.x*blockDim.x+threadIdx.x;
    if(i<Ea){
        int d=ea[Ea+i];
        if(d<B){ int p=atomicAdd(&ua[d],1); sa[p]=ea[i]; da[p]=d; }
    } else if(i<Ea+Ep){
        int j=i-Ea; int d=ep[Ep+j];
        if(d<B){ int p=atomicAdd(&up[d],1); sp[p]=ep[j]; }
    }
}

// edge logits via HMMA bf16-split: per CTA 128 gathered edge rows x 128 cols, K=128
__global__ void __launch_bounds__(256) k_emma(
    const float* __restrict__ xa,const u32* __restrict__ Bh,const u32* __restrict__ Bl,
    const float* __restrict__ blv,const int* __restrict__ srcs,const int* __restrict__ tot,
    const int* __restrict__ darr,const float* __restrict__ xr,
    const float* __restrict__ att,float* __restrict__ lg){
    extern __shared__ char sm[];
    u32* ah=(u32*)sm;          // A hi  [128][66 words]
    u32* al=ah+8448;           // A lo
    u32* bh=al+8448;           // B hi  [128][66 words]
    u32* bw=bh+8448;           // B lo
    int total=*tot;
    int row0=blockIdx.x*128;
    if(row0>=total) return;
    int t=threadIdx.x,wid=t>>5,lane=t&31;
    // stage B: copy padded images verbatim
    for(int i=t;i<2112;i+=256){ ((uint4*)bh)[i]=((const uint4*)Bh)[i]; ((uint4*)bw)[i]=((const uint4*)Bl)[i]; }
    // stage A: gather + hi/lo split into padded row-major
    {
        int m=t>>1,hh=t&1;
        int r=row0+m;
        int rr=(r<total)?srcs[r]:0;
        const float4* X4=(const float4*)xa;
#pragma unroll
        for(int j=0;j<16;j++){
            float4 v=X4[(size_t)rr*32+hh*16+j];
            u32 w0=cbf2(v.x,v.y),w1=cbf2(v.z,v.w);
            u32 g0=cbf2(v.x-blo(w0),v.y-bhi(w0));
            u32 g1=cbf2(v.z-blo(w1),v.w-bhi(w1));
            int base=m*66+hh*32+j*2;
            ah[base]=w0; ah[base+1]=w1; al[base]=g0; al[base+1]=g1;
        }
    }
    __syncthreads();
    int g=lane>>2,tt=lane&3;
    int m0=wid*16;
    float acc[16][4];
#pragma unroll
    for(int j=0;j<16;j++){ acc[j][0]=0.f;acc[j][1]=0.f;acc[j][2]=0.f;acc[j][3]=0.f; }
    int rA=(m0+g)*66,rB=(m0+g+8)*66;
#pragma unroll
    for(int ks=0;ks<8;ks++){
        int kb=ks*8+tt;
        u32 a0=ah[rA+kb],a1=ah[rB+kb],a2=ah[rA+kb+4],a3=ah[rB+kb+4];
        u32 l0=al[rA+kb],l1=al[rB+kb],l2=al[rA+kb+4],l3=al[rB+kb+4];
#pragma unroll
        for(int j=0;j<16;j++){
            int nb=(8*j+g)*66+kb;
            u32 b0=bh[nb],b1=bh[nb+4];
            u32 c0=bw[nb],c1=bw[nb+4];
            mmab(acc[j],a0,a1,a2,a3,b0,b1);
            mmab(acc[j],a0,a1,a2,a3,c0,c1);
            mmab(acc[j],l0,l1,l2,l3,b0,b1);
        }
    }
    // epilogue: lane owns cols 8j+2tt(+1) for rows m0+g and m0+g+8
    int ra=row0+m0+g,rb=ra+8;
    int dda=(ra<total)?darr[ra]:0,ddb=(rb<total)?darr[rb]:0;
    const float2* XRa=(const float2*)xr+(size_t)dda*64;
    const float2* XRb=(const float2*)xr+(size_t)ddb*64;
    const float2* AT=(const float2*)att;
    const float2* BL=(const float2*)blv;
    float pa=0.f,pb=0.f;
#pragma unroll
    for(int j=0;j<16;j++){
        int ci=j*4+tt;
        float2 av=AT[ci],bv=BL[ci],x1=XRa[ci],x2=XRb[ci];
        pa+=av.x*lrelu(acc[j][0]+bv.x+x1.x)+av.y*lrelu(acc[j][1]+bv.y+x1.y);
        pb+=av.x*lrelu(acc[j][2]+bv.x+x2.x)+av.y*lrelu(acc[j][3]+bv.y+x2.y);
    }
    pa+=__shfl_xor_sync(0xffffffffu,pa,1); pa+=__shfl_xor_sync(0xffffffffu,pa,2);
    pb+=__shfl_xor_sync(0xffffffffu,pb,1); pb+=__shfl_xor_sync(0xffffffffu,pb,2);
    if(tt==0){
        if(ra<total) lg[ra]=pa;
        if(rb<total) lg[rb]=pb;
    }
}

// fp32 128x128 GEMM, k-chunk double-buffered. MODE 0: Y=X@W+b1; MODE 2: +b2+addmat
template <int MODE>
__global__ void __launch_bounds__(256) k_gemm(
    const float* __restrict__ X,const float* __restrict__ W,
    const float* __restrict__ b1,const float* __restrict__ b2,
    float* __restrict__ Y,int total,const float* __restrict__ am){
    int row0=blockIdx.x*128;
    if(row0>=total) return;
    __shared__ float Ws[2][16][128];
    __shared__ float Xs[2][16][128];
    int t=threadIdx.x,tx=t&15,ty=t>>4;
    int tx8=tx*8,ty8=ty*8;
    int ma=t>>2,kq=t&3,mb=ma+64;
    int kwa=t>>5,nw=t&31,kwb=kwa+8;
    int rra=(row0+ma<total)?row0+ma:0;
    int rrb=(row0+mb<total)?row0+mb:0;
    const float4* X4=(const float4*)X;
    const float4* W4=(const float4*)W;
    u64 acc[8][4];
    {
        float4 q0=((const float4*)b1)[tx*2],q1=((const float4*)b1)[tx*2+1];
        if(MODE==2){
            float4 p0=((const float4*)b2)[tx*2],p1=((const float4*)b2)[tx*2+1];
            q0.x+=p0.x;q0.y+=p0.y;q0.z+=p0.z;q0.w+=p0.w;
            q1.x+=p1.x;q1.y+=p1.y;q1.z+=p1.z;q1.w+=p1.w;
        }
        u64 i0=pack2(q0.x,q0.y),i1=pack2(q0.z,q0.w),i2=pack2(q1.x,q1.y),i3=pack2(q1.z,q1.w);
#pragma unroll
        for(int r=0;r<8;r++){ acc[r][0]=i0;acc[r][1]=i1;acc[r][2]=i2;acc[r][3]=i3; }
    }
    float4 va=X4[(size_t)rra*32+kq];
    float4 vb=X4[(size_t)rrb*32+kq];
    float4 wa=W4[kwa*32+nw];
    float4 wb=W4[kwb*32+nw];
    ((float4*)&Ws[0][kwa][nw*4])[0]=wa;
    ((float4*)&Ws[0][kwb][nw*4])[0]=wb;
    Xs[0][kq*4+0][ma]=va.x; Xs[0][kq*4+1][ma]=va.y; Xs[0][kq*4+2][ma]=va.z; Xs[0][kq*4+3][ma]=va.w;
    Xs[0][kq*4+0][mb]=vb.x; Xs[0][kq*4+1][mb]=vb.y; Xs[0][kq*4+2][mb]=vb.z; Xs[0][kq*4+3][mb]=vb.w;
    __syncthreads();
#pragma unroll
    for(int c=0;c<8;c++){
        int buf=c&1;
        if(c<7){
            va=X4[(size_t)rra*32+(c+1)*4+kq];
            vb=X4[(size_t)rrb*32+(c+1)*4+kq];
            wa=W4[((c+1)*16+kwa)*32+nw];
            wb=W4[((c+1)*16+kwb)*32+nw];
        }
#pragma unroll
        for(int kk=0;kk<16;kk++){
            float4 a0=*(const float4*)&Xs[buf][kk][ty8];
            float4 a1=*(const float4*)&Xs[buf][kk][ty8+4];
            ulonglong2 b01=*(const ulonglong2*)&Ws[buf][kk][tx8];
            ulonglong2 b23=*(const ulonglong2*)&Ws[buf][kk][tx8+4];
            float av[8]={a0.x,a0.y,a0.z,a0.w,a1.x,a1.y,a1.z,a1.w};
#pragma unroll
            for(int r=0;r<8;r++){
                u64 s=splat2(av[r]);
                acc[r][0]=ffma2(s,b01.x,acc[r][0]);
                acc[r][1]=ffma2(s,b01.y,acc[r][1]);
                acc[r][2]=ffma2(s,b23.x,acc[r][2]);
                acc[r][3]=ffma2(s,b23.y,acc[r][3]);
            }
        }
        if(c<7){
            int nb=buf^1;
            ((float4*)&Ws[nb][kwa][nw*4])[0]=wa;
            ((float4*)&Ws[nb][kwb][nw*4])[0]=wb;
            Xs[nb][kq*4+0][ma]=va.x; Xs[nb][kq*4+1][ma]=va.y; Xs[nb][kq*4+2][ma]=va.z; Xs[nb][kq*4+3][ma]=va.w;
            Xs[nb][kq*4+0][mb]=vb.x; Xs[nb][kq*4+1][mb]=vb.y; Xs[nb][kq*4+2][mb]=vb.z; Xs[nb][kq*4+3][mb]=vb.w;
            __syncthreads();
        }
    }
#pragma unroll
    for(int r=0;r<8;r++){
        int row=row0+ty8+r;
        if(row<total){
            float2 v0=unpack2(acc[r][0]),v1=unpack2(acc[r][1]),v2=unpack2(acc[r][2]),v3=unpack2(acc[r][3]);
            float4 o0=make_float4(v0.x,v0.y,v1.x,v1.y);
            float4 o1=make_float4(v2.x,v2.y,v3.x,v3.y);
            if(MODE==2){
                float4 m0=((const float4*)am)[(size_t)row*32+tx*2];
                float4 m1=((const float4*)am)[(size_t)row*32+tx*2+1];
                o0.x+=m0.x;o0.y+=m0.y;o0.z+=m0.z;o0.w+=m0.w;
                o1.x+=m1.x;o1.y+=m1.y;o1.z+=m1.z;o1.w+=m1.w;
            }
            ((float4*)Y)[(size_t)row*32+tx*2]=o0;
            ((float4*)Y)[(size_t)row*32+tx*2+1]=o1;
        }
    }
}

__global__ void __launch_bounds__(256) k_agg(
    const float* __restrict__ xa,const float* __restrict__ lg,
    const int* __restrict__ oa,const int* __restrict__ sa,
    const float* __restrict__ xlpp,const float* __restrict__ xrpp,
    const float* __restrict__ attp,const float* __restrict__ bsp,
    const int* __restrict__ op,const int* __restrict__ sp,
    float* __restrict__ accap,float* __restrict__ ppo){
    int t=threadIdx.x,lane=t&31,warp=t>>5;
    int dst=blockIdx.x*8+warp;
    int e0=oa[dst],e1=oa[dst+1];
    float4 acc=make_float4(0.f,0.f,0.f,0.f);
    if(e1>e0){
        float m=-INFINITY,den=0.f;
        for(int base=e0;base<e1;base+=32){
            int e=base+lane;
            bool v=(e<e1);
            float le=v?lg[e]:-INFINITY;
            float cm=le;
#pragma unroll
            for(int o=16;o;o>>=1) cm=fmaxf(cm,__shfl_xor_sync(0xffffffffu,cm,o));
            if(cm>m){ den*=__expf(m-cm); m=cm; }
            float w=v?__expf(le-m):0.f;
#pragma unroll
            for(int o=16;o;o>>=1) w+=__shfl_xor_sync(0xffffffffu,w,o);
            den+=w;
        }
        float inv=1.f/den;
        int e=e0;
        for(;e+3<e1;e+=4){
            int s0=sa[e],s1=sa[e+1],s2=sa[e+2],s3=sa[e+3];
            float4 x0=((const float4*)xa)[(size_t)s0*32+lane];
            float4 x1=((const float4*)xa)[(size_t)s1*32+lane];
            float4 x2=((const float4*)xa)[(size_t)s2*32+lane];
            float4 x3=((const float4*)xa)[(size_t)s3*32+lane];
            float a0=__expf(lg[e]-m)*inv,a1=__expf(lg[e+1]-m)*inv;
            float a2=__expf(lg[e+2]-m)*inv,a3=__expf(lg[e+3]-m)*inv;
            acc.x+=a0*x0.x+a1*x1.x+a2*x2.x+a3*x3.x;
            acc.y+=a0*x0.y+a1*x1.y+a2*x2.y+a3*x3.y;
            acc.z+=a0*x0.z+a1*x1.z+a2*x2.z+a3*x3.z;
            acc.w+=a0*x0.w+a1*x1.w+a2*x2.w+a3*x3.w;
        }
        for(;e<e1;e++){
            float a0=__expf(lg[e]-m)*inv;
            float4 x0=((const float4*)xa)[(size_t)sa[e]*32+lane];
            acc.x+=a0*x0.x; acc.y+=a0*x0.y; acc.z+=a0*x0.z; acc.w+=a0*x0.w;
        }
    }
    ((float4*)accap)[(size_t)dst*32+lane]=acc;

    float4 attv=((const float4*)attp)[lane];
    float4 bsv=((const float4*)bsp)[lane];
    float4 xrv=((const float4*)xrpp)[(size_t)dst*32+lane];
    float m=-INFINITY,den=0.f;
    float4 pa=make_float4(0.f,0.f,0.f,0.f);
    int p0=op[dst],p1=op[dst+1];
    for(int eb=p0;eb<p1;eb+=4){
        int g=min(4,p1-eb);
        int sl=(lane<g)?sp[eb+lane]:0;
        float4 xv[4];
        float lgv[4];
#pragma unroll
        for(int i=0;i<4;i++){
            if(i<g){
                int row=__shfl_sync(0xffffffffu,sl,i);
                xv[i]=((const float4*)xlpp)[(size_t)row*32+lane];
            }
        }
#pragma unroll
        for(int i=0;i<4;i++){
            if(i<g){
                float p=lrelu(xv[i].x+xrv.x)*attv.x+lrelu(xv[i].y+xrv.y)*attv.y
                       +lrelu(xv[i].z+xrv.z)*attv.z+lrelu(xv[i].w+xrv.w)*attv.w;
#pragma unroll
                for(int o=16;o;o>>=1) p+=__shfl_xor_sync(0xffffffffu,p,o);
                lgv[i]=p;
            }
        }
        float gm=m;
#pragma unroll
        for(int i=0;i<4;i++) if(i<g) gm=fmaxf(gm,lgv[i]);
        float sc=__expf(m-gm);
        den*=sc; pa.x*=sc; pa.y*=sc; pa.z*=sc; pa.w*=sc;
#pragma unroll
        for(int i=0;i<4;i++){
            if(i<g){
                float w=__expf(lgv[i]-gm);
                den+=w;
                pa.x+=w*xv[i].x; pa.y+=w*xv[i].y; pa.z+=w*xv[i].z; pa.w+=w*xv[i].w;
            }
        }
        m=gm;
    }
    float inv2=(den>0.f)?1.f/den:0.f;
    pa.x=pa.x*inv2+bsv.x; pa.y=pa.y*inv2+bsv.y; pa.z=pa.z*inv2+bsv.z; pa.w=pa.w*inv2+bsv.w;
    ((float4*)ppo)[(size_t)dst*32+lane]=pa;
}

__global__ void __launch_bounds__(256) k_final(
    const float* __restrict__ hid,const float* __restrict__ Wl,
    const float* __restrict__ bl,float* __restrict__ out){
    extern __shared__ char sm[];
    float* Ws=(float*)sm;
    float* hs=(float*)sm+D*DOUT;
    int t=threadIdx.x,lane=t&31,warp=t>>5;
    for(int i=t;i<D*DOUT/4;i+=256) ((float4*)Ws)[i]=((const float4*)Wl)[i];
    int row0=blockIdx.x*32+warp*4;
#pragma unroll
    for(int r=0;r<4;r++){
        float4 h=((const float4*)hid)[(size_t)(row0+r)*32+lane];
        h.x=fmaxf(h.x,0.f); h.y=fmaxf(h.y,0.f); h.z=fmaxf(h.z,0.f); h.w=fmaxf(h.w,0.f);
        ((float4*)&hs[(warp*4+r)*D])[lane]=h;
    }
    __syncthreads();
    float b0=bl[lane],b1=bl[lane+32];
    float a0[4],a1[4];
#pragma unroll
    for(int r=0;r<4;r++){ a0[r]=b0; a1[r]=b1; }
    for(int k=0;k<D;k++){
        float w0=Ws[k*DOUT+lane],w1=Ws[k*DOUT+lane+32];
#pragma unroll
        for(int r=0;r<4;r++){
            float h=hs[(warp*4+r)*D+k];
            a0[r]+=h*w0; a1[r]+=h*w1;
        }
    }
#pragma unroll
    for(int r=0;r<4;r++){
        int row=row0+r;
        out[(size_t)row*DOUT+lane]=a0[r];
        out[(size_t)row*DOUT+lane+32]=a1[r];
    }
}

extern "C" void kernel_launch(void* const* d_in,const int* in_sizes,int n_in,
                              void* d_out,int out_size){
    const float* xa=(const float*)d_in[0];
    const float* xp=(const float*)d_in[1];
    const int* ea=(const int*)d_in[2];
    const int* ep=(const int*)d_in[3];
    const float* Wla=(const float*)d_in[5];
    const float* bla=(const float*)d_in[6];
    const float* Wra=(const float*)d_in[7];
    const float* bra=(const float*)d_in[8];
    const float* ata=(const float*)d_in[9];
    const float* bsa=(const float*)d_in[10];
    const float* Wlp=(const float*)d_in[11];
    const float* blp=(const float*)d_in[12];
    const float* Wrp=(const float*)d_in[13];
    const float* brp=(const float*)d_in[14];
    const float* atp=(const float*)d_in[15];
    const float* bsp=(const float*)d_in[16];
    const float* Wf=(const float*)d_in[17];
    const float* bf=(const float*)d_in[18];
    float* out=(float*)d_out;
    int Ea=in_sizes[2]/2,Ep=in_sizes[3]/2,Eb=Ea+Ep;

    void* p;
    cudaGetSymbolAddress(&p,g_xlpp); float* xlpp=(float*)p;
    cudaGetSymbolAddress(&p,g_xrpp); float* xrpp=(float*)p;
    cudaGetSymbolAddress(&p,g_xrap); float* xrap=(float*)p;
    cudaGetSymbolAddress(&p,g_hid);  float* hid=(float*)p;
    cudaGetSymbolAddress(&p,g_acc);  float* accap=(float*)p;
    cudaGetSymbolAddress(&p,g_ppo);  float* ppo=(float*)p;
    cudaGetSymbolAddress(&p,g_lg);   float* lg=(float*)p;
    cudaGetSymbolAddress(&p,g_Bh);   u32* Bh=(u32*)p;
    cudaGetSymbolAddress(&p,g_Bl);   u32* Bl=(u32*)p;
    cudaGetSymbolAddress(&p,g_ca);   int* ca=(int*)p;
    cudaGetSymbolAddress(&p,g_cp);   int* cp=(int*)p;
    cudaGetSymbolAddress(&p,g_oa);   int* oa=(int*)p;
    cudaGetSymbolAddress(&p,g_op);   int* op=(int*)p;
    cudaGetSymbolAddress(&p,g_ua);   int* ua=(int*)p;
    cudaGetSymbolAddress(&p,g_up);   int* up=(int*)p;
    cudaGetSymbolAddress(&p,g_sa);   int* sa=(int*)p;
    cudaGetSymbolAddress(&p,g_da);   int* da=(int*)p;
    cudaGetSymbolAddress(&p,g_sp);   int* sp=(int*)p;

    cudaFuncSetAttribute(k_emma,cudaFuncAttributeMaxDynamicSharedMemorySize,135168);
    cudaFuncSetAttribute(k_final,cudaFuncAttributeMaxDynamicSharedMemorySize,49152);

    // 0: zero hists + prep B images
    k_zero<<<(2*B+16384+255)/256,256>>>(ca,cp,Wla,Bh,Bl);
    // 1-3: hist, scan, scatter
    k_hist<<<(Eb+255)/256,256>>>(ea,Ea,ca,ep,Ep,cp);
    k_scan<<<2,1024>>>(ca,oa,ua,cp,op,up);
    k_scat<<<(Eb+255)/256,256>>>(ea,Ea,ua,sa,da,ep,Ep,up,sp);
    // 4: xr_ap (needed by emma epilogue)
    k_gemm<0><<<B/128,256>>>(xp,Wra,bra,nullptr,xrap,B,nullptr);
    // 5 (ncu slot): HMMA edge GEMM -> logits
    k_emma<<<(EA+127)/128,256,135168>>>(xa,Bh,Bl,bla,sa,&oa[B],da,xrap,ata,lg);
    // 6-7: PP node transforms
    k_gemm<0><<<(NP+127)/128,256>>>(xp,Wlp,blp,nullptr,xlpp,NP,nullptr);
    k_gemm<0><<<B/128,256>>>(xp,Wrp,brp,nullptr,xrpp,B,nullptr);
    // 8: fused AP + PP aggregation
    k_agg<<<B/8,256>>>(xa,lg,oa,sa,xlpp,xrpp,atp,bsp,op,sp,accap,ppo);
    // 9: hid = accap @ Wl_ap + bl + bias + ppo
    k_gemm<2><<<B/128,256>>>(accap,Wla,bla,bsa,hid,B,ppo);
    // 10: relu + final linear
    k_final<<<B/32,256,49152>>>(hid,Wf,bf,out);
}

// round 11
// speedup vs baseline: 1.1606x; 1.0803x over previous
#include <cuda_runtime.h>
#include <cuda_bf16.h>
#include <stdint.h>
#include <math.h>
#define D 128
#define DOUT 64
#define NP 30000
#define EA 300000
#define EP 960000
#define B 16384
#define NEG 0.2f
typedef unsigned long long u64;
typedef unsigned int u32;

__device__ float g_xlpp[NP*D];
__device__ float g_xrpp[B*D];
__device__ float g_xrap[B*D];
__device__ float g_hid[B*D];
__device__ float g_acc[B*D];
__device__ float g_ppo[B*D];
__device__ float g_lg[EA];
__device__ u64 g_Bfh[4096];   // per-lane B fragments [ks][j][lane], bf16-hi
__device__ u64 g_Bfl[4096];   // bf16-lo residual fragments
__device__ int g_ca[B], g_cp[B], g_oa[B+1], g_op[B+1], g_ua[B], g_up[B];
__device__ int g_sa[EA], g_da[EA], g_sp[EP];

__device__ __forceinline__ float lrelu(float x){ return x>0.f?x:NEG*x; }
__device__ __forceinline__ u64 splat2(float x){ u64 d; asm("mov.b64 %0,{%1,%1};":"=l"(d):"r"(__float_as_uint(x))); return d; }
__device__ __forceinline__ u64 pack2(float a,float b){ u64 d; asm("mov.b64 %0,{%1,%2};":"=l"(d):"r"(__float_as_uint(a)),"r"(__float_as_uint(b))); return d; }
__device__ __forceinline__ float2 unpack2(u64 u){ float2 f; asm("mov.b64 {%0,%1},%2;":"=f"(f.x),"=f"(f.y):"l"(u)); return f; }
__device__ __forceinline__ u64 ffma2(u64 a,u64 b,u64 c){ u64 d; asm("fma.rn.f32x2 %0,%1,%2,%3;":"=l"(d):"l"(a),"l"(b),"l"(c)); return d; }
__device__ __forceinline__ u32 cbf2(float lo,float hi){ u32 r; asm("cvt.rn.bf16x2.f32 %0,%1,%2;":"=r"(r):"f"(hi),"f"(lo)); return r; }
__device__ __forceinline__ float blo(u32 r){ return __uint_as_float(r<<16); }
__device__ __forceinline__ float bhi(u32 r){ return __uint_as_float(r&0xffff0000u); }
__device__ __forceinline__ void mmab(float* c,u32 a0,u32 a1,u32 a2,u32 a3,u32 b0,u32 b1){
    asm volatile("mma.sync.aligned.m16n8k16.row.col.f32.bf16.bf16.f32 "
        "{%0,%1,%2,%3},{%4,%5,%6,%7},{%8,%9},{%0,%1,%2,%3};"
        :"+f"(c[0]),"+f"(c[1]),"+f"(c[2]),"+f"(c[3])
        :"r"(a0),"r"(a1),"r"(a2),"r"(a3),"r"(b0),"r"(b1));
}

// zero histograms + build per-lane B fragment images from Wla [k][n]
__global__ void k_zero(int* a,int* b,const float* W,u64* fh,u64* fl){
    int i=blockIdx.x*blockDim.x+threadIdx.x;
    if(i<B) a[i]=0;
    else if(i<2*B) b[i-B]=0;
    else if(i<2*B+4096){
        int idx=i-2*B;
        int ks=idx>>9, j=(idx>>5)&15, ln=idx&31;
        int n=8*j+(ln>>2), kw=ks*8+(ln&3);
        float v00=W[(2*kw)*128+n],   v01=W[(2*kw+1)*128+n];
        float v10=W[(2*kw+8)*128+n], v11=W[(2*kw+9)*128+n];
        u32 w0=cbf2(v00,v01), w1=cbf2(v10,v11);
        u32 g0=cbf2(v00-blo(w0),v01-bhi(w0));
        u32 g1=cbf2(v10-blo(w1),v11-bhi(w1));
        fh[idx]=(u64)w0|((u64)w1<<32);
        fl[idx]=(u64)g0|((u64)g1<<32);
    }
}
__global__ void k_hist(const int* ea,int Ea,int* ca,const int* ep,int Ep,int* cp){
    int i=blockIdx.x*blockDim.x+threadIdx.x;
    if(i<Ea){ int d=ea[Ea+i]; if(d<B) atomicAdd(&ca[d],1); }
    else if(i<Ea+Ep){ int d=ep[Ep+i-Ea]; if(d<B) atomicAdd(&cp[d],1); }
}
__global__ void k_scan(const int* ca,int* oa,int* ua,const int* cp,int* op,int* up){
    const int* cnt=blockIdx.x?cp:ca;
    int* off=blockIdx.x?op:oa;
    int* cur=blockIdx.x?up:ua;
    __shared__ int s[1024];
    int t=threadIdx.x,v[16],run=0;
#pragma unroll
    for(int i=0;i<16;i++){ v[i]=run; run+=cnt[t*16+i]; }
    s[t]=run; __syncthreads();
    for(int d=1;d<1024;d<<=1){
        int add=(t>=d)?s[t-d]:0; __syncthreads();
        s[t]+=add; __syncthreads();
    }
    int base=(t>0)?s[t-1]:0;
#pragma unroll
    for(int i=0;i<16;i++){ int o=base+v[i]; off[t*16+i]=o; cur[t*16+i]=o; }
    if(t==1023) off[16384]=s[1023];
}
__global__ void k_scat(const int* ea,int Ea,int* ua,int* sa,int* da,const int* ep,int Ep,int* up,int* sp){
    int i=blockIdx.x*blockDim.x+threadIdx.x;
    if(i<Ea){
        int d=ea[Ea+i];
        if(d<B){ int p=atomicAdd(&ua[d],1); sa[p]=ea[i]; da[p]=d; }
    } else if(i<Ea+Ep){
        int j=i-Ea; int d=ep[Ep+j];
        if(d<B){ int p=atomicAdd(&up[d],1); sp[p]=ep[j]; }
    }
}

// edge logits via HMMA bf16-split, pipelined accumulator chains
__global__ void __launch_bounds__(256) k_emma(
    const float* __restrict__ xa,const u64* __restrict__ Bfh,const u64* __restrict__ Bfl,
    const float* __restrict__ blv,const int* __restrict__ srcs,const int* __restrict__ tot,
    const int* __restrict__ darr,const float* __restrict__ xr,
    const float* __restrict__ att,float* __restrict__ lg){
    extern __shared__ char sm[];
    u32* ah=(u32*)sm;              // A hi [128][68 words] = 34816 B
    u32* al=ah+8704;               // A lo
    u64* bh=(u64*)(al+8704);       // 4096 u64 = 32768 B
    u64* bw=bh+4096;
    int total=*tot;
    int row0=blockIdx.x*128;
    if(row0>=total) return;
    int t=threadIdx.x,wid=t>>5,lane=t&31;
    // stage B fragment images
    for(int i=t;i<2048;i+=256){ ((uint4*)bh)[i]=((const uint4*)Bfh)[i]; ((uint4*)bw)[i]=((const uint4*)Bfl)[i]; }
    // stage A: gather + hi/lo split, padded stride 68 (conflict-free reads)
    {
        int m=t>>1,hh=t&1;
        int r=row0+m;
        int rr=(r<total)?srcs[r]:0;
        const float4* X4=(const float4*)xa;
        int base=m*68+hh*32;
#pragma unroll
        for(int j=0;j<16;j++){
            float4 v=X4[(size_t)rr*32+hh*16+j];
            u32 w0=cbf2(v.x,v.y),w1=cbf2(v.z,v.w);
            u32 g0=cbf2(v.x-blo(w0),v.y-bhi(w0));
            u32 g1=cbf2(v.z-blo(w1),v.w-bhi(w1));
            ah[base+j*2]=w0; ah[base+j*2+1]=w1;
            al[base+j*2]=g0; al[base+j*2+1]=g1;
        }
    }
    __syncthreads();
    int g=lane>>2,tt=lane&3,m0=wid*16;
    float P[16][4],Q[16][4];
#pragma unroll
    for(int j=0;j<16;j++){
        P[j][0]=0.f;P[j][1]=0.f;P[j][2]=0.f;P[j][3]=0.f;
        Q[j][0]=0.f;Q[j][1]=0.f;Q[j][2]=0.f;Q[j][3]=0.f;
    }
    int rA=(m0+g)*68,rB=rA+544;
#pragma unroll
    for(int ks=0;ks<8;ks++){
        int kb=ks*8+tt;
        u32 a0=ah[rA+kb],a1=ah[rB+kb],a2=ah[rA+kb+4],a3=ah[rB+kb+4];
        u32 l0=al[rA+kb],l1=al[rB+kb],l2=al[rA+kb+4],l3=al[rB+kb+4];
        const u64* bp=bh+ks*512+lane;
        const u64* cp2=bw+ks*512+lane;
        // phase 1: hh -> P, lh -> Q (independent chains, B-hi loaded once)
#pragma unroll
        for(int j=0;j<16;j++){
            u64 bb=bp[j*32];
            u32 b0=(u32)bb,b1=(u32)(bb>>32);
            mmab(P[j],a0,a1,a2,a3,b0,b1);
            mmab(Q[j],l0,l1,l2,l3,b0,b1);
        }
        // phase 2: hl -> P (distance >=16 from phase-1 writes)
#pragma unroll
        for(int j=0;j<16;j++){
            u64 cc=cp2[j*32];
            u32 c0=(u32)cc,c1=(u32)(cc>>32);
            mmab(P[j],a0,a1,a2,a3,c0,c1);
        }
    }
    // epilogue: lane owns cols 8j+2tt(+1) for rows m0+g and m0+g+8
    int ra=row0+m0+g,rb=ra+8;
    int dda=(ra<total)?darr[ra]:0,ddb=(rb<total)?darr[rb]:0;
    const float2* XRa=(const float2*)xr+(size_t)dda*64;
    const float2* XRb=(const float2*)xr+(size_t)ddb*64;
    const float2* AT=(const float2*)att;
    const float2* BL=(const float2*)blv;
    float pa=0.f,pb=0.f;
#pragma unroll
    for(int j=0;j<16;j++){
        int ci=j*4+tt;
        float2 av=AT[ci],bv=BL[ci],x1=XRa[ci],x2=XRb[ci];
        float d0=P[j][0]+Q[j][0],d1=P[j][1]+Q[j][1];
        float d2=P[j][2]+Q[j][2],d3=P[j][3]+Q[j][3];
        pa+=av.x*lrelu(d0+bv.x+x1.x)+av.y*lrelu(d1+bv.y+x1.y);
        pb+=av.x*lrelu(d2+bv.x+x2.x)+av.y*lrelu(d3+bv.y+x2.y);
    }
    pa+=__shfl_xor_sync(0xffffffffu,pa,1); pa+=__shfl_xor_sync(0xffffffffu,pa,2);
    pb+=__shfl_xor_sync(0xffffffffu,pb,1); pb+=__shfl_xor_sync(0xffffffffu,pb,2);
    if(tt==0){
        if(ra<total) lg[ra]=pa;
        if(rb<total) lg[rb]=pb;
    }
}

// fp32 128x128 GEMM, k-chunk double-buffered. MODE 0: Y=X@W+b1; MODE 2: +b2+addmat
template <int MODE>
__global__ void __launch_bounds__(256) k_gemm(
    const float* __restrict__ X,const float* __restrict__ W,
    const float* __restrict__ b1,const float* __restrict__ b2,
    float* __restrict__ Y,int total,const float* __restrict__ am){
    int row0=blockIdx.x*128;
    if(row0>=total) return;
    __shared__ float Ws[2][16][128];
    __shared__ float Xs[2][16][128];
    int t=threadIdx.x,tx=t&15,ty=t>>4;
    int tx8=tx*8,ty8=ty*8;
    int ma=t>>2,kq=t&3,mb=ma+64;
    int kwa=t>>5,nw=t&31,kwb=kwa+8;
    int rra=(row0+ma<total)?row0+ma:0;
    int rrb=(row0+mb<total)?row0+mb:0;
    const float4* X4=(const float4*)X;
    const float4* W4=(const float4*)W;
    u64 acc[8][4];
    {
        float4 q0=((const float4*)b1)[tx*2],q1=((const float4*)b1)[tx*2+1];
        if(MODE==2){
            float4 p0=((const float4*)b2)[tx*2],p1=((const float4*)b2)[tx*2+1];
            q0.x+=p0.x;q0.y+=p0.y;q0.z+=p0.z;q0.w+=p0.w;
            q1.x+=p1.x;q1.y+=p1.y;q1.z+=p1.z;q1.w+=p1.w;
        }
        u64 i0=pack2(q0.x,q0.y),i1=pack2(q0.z,q0.w),i2=pack2(q1.x,q1.y),i3=pack2(q1.z,q1.w);
#pragma unroll
        for(int r=0;r<8;r++){ acc[r][0]=i0;acc[r][1]=i1;acc[r][2]=i2;acc[r][3]=i3; }
    }
    float4 va=X4[(size_t)rra*32+kq];
    float4 vb=X4[(size_t)rrb*32+kq];
    float4 wa=W4[kwa*32+nw];
    float4 wb=W4[kwb*32+nw];
    ((float4*)&Ws[0][kwa][nw*4])[0]=wa;
    ((float4*)&Ws[0][kwb][nw*4])[0]=wb;
    Xs[0][kq*4+0][ma]=va.x; Xs[0][kq*4+1][ma]=va.y; Xs[0][kq*4+2][ma]=va.z; Xs[0][kq*4+3][ma]=va.w;
    Xs[0][kq*4+0][mb]=vb.x; Xs[0][kq*4+1][mb]=vb.y; Xs[0][kq*4+2][mb]=vb.z; Xs[0][kq*4+3][mb]=vb.w;
    __syncthreads();
#pragma unroll
    for(int c=0;c<8;c++){
        int buf=c&1;
        if(c<7){
            va=X4[(size_t)rra*32+(c+1)*4+kq];
            vb=X4[(size_t)rrb*32+(c+1)*4+kq];
            wa=W4[((c+1)*16+kwa)*32+nw];
            wb=W4[((c+1)*16+kwb)*32+nw];
        }
#pragma unroll
        for(int kk=0;kk<16;kk++){
            float4 a0=*(const float4*)&Xs[buf][kk][ty8];
            float4 a1=*(const float4*)&Xs[buf][kk][ty8+4];
            ulonglong2 b01=*(const ulonglong2*)&Ws[buf][kk][tx8];
            ulonglong2 b23=*(const ulonglong2*)&Ws[buf][kk][tx8+4];
            float av[8]={a0.x,a0.y,a0.z,a0.w,a1.x,a1.y,a1.z,a1.w};
#pragma unroll
            for(int r=0;r<8;r++){
                u64 s=splat2(av[r]);
                acc[r][0]=ffma2(s,b01.x,acc[r][0]);
                acc[r][1]=ffma2(s,b01.y,acc[r][1]);
                acc[r][2]=ffma2(s,b23.x,acc[r][2]);
                acc[r][3]=ffma2(s,b23.y,acc[r][3]);
            }
        }
        if(c<7){
            int nb=buf^1;
            ((float4*)&Ws[nb][kwa][nw*4])[0]=wa;
            ((float4*)&Ws[nb][kwb][nw*4])[0]=wb;
            Xs[nb][kq*4+0][ma]=va.x; Xs[nb][kq*4+1][ma]=va.y; Xs[nb][kq*4+2][ma]=va.z; Xs[nb][kq*4+3][ma]=va.w;
            Xs[nb][kq*4+0][mb]=vb.x; Xs[nb][kq*4+1][mb]=vb.y; Xs[nb][kq*4+2][mb]=vb.z; Xs[nb][kq*4+3][mb]=vb.w;
            __syncthreads();
        }
    }
#pragma unroll
    for(int r=0;r<8;r++){
        int row=row0+ty8+r;
        if(row<total){
            float2 v0=unpack2(acc[r][0]),v1=unpack2(acc[r][1]),v2=unpack2(acc[r][2]),v3=unpack2(acc[r][3]);
            float4 o0=make_float4(v0.x,v0.y,v1.x,v1.y);
            float4 o1=make_float4(v2.x,v2.y,v3.x,v3.y);
            if(MODE==2){
                float4 m0=((const float4*)am)[(size_t)row*32+tx*2];
                float4 m1=((const float4*)am)[(size_t)row*32+tx*2+1];
                o0.x+=m0.x;o0.y+=m0.y;o0.z+=m0.z;o0.w+=m0.w;
                o1.x+=m1.x;o1.y+=m1.y;o1.z+=m1.z;o1.w+=m1.w;
            }
            ((float4*)Y)[(size_t)row*32+tx*2]=o0;
            ((float4*)Y)[(size_t)row*32+tx*2+1]=o1;
        }
    }
}

__global__ void __launch_bounds__(256) k_agg(
    const float* __restrict__ xa,const float* __restrict__ lg,
    const int* __restrict__ oa,const int* __restrict__ sa,
    const float* __restrict__ xlpp,const float* __restrict__ xrpp,
    const float* __restrict__ attp,const float* __restrict__ bsp,
    const int* __restrict__ op,const int* __restrict__ sp,
    float* __restrict__ accap,float* __restrict__ ppo){
    int t=threadIdx.x,lane=t&31,warp=t>>5;
    int dst=blockIdx.x*8+warp;
    int e0=oa[dst],e1=oa[dst+1];
    float4 acc=make_float4(0.f,0.f,0.f,0.f);
    if(e1>e0){
        float m=-INFINITY,den=0.f;
        for(int base=e0;base<e1;base+=32){
            int e=base+lane;
            bool v=(e<e1);
            float le=v?lg[e]:-INFINITY;
            float cm=le;
#pragma unroll
            for(int o=16;o;o>>=1) cm=fmaxf(cm,__shfl_xor_sync(0xffffffffu,cm,o));
            if(cm>m){ den*=__expf(m-cm); m=cm; }
            float w=v?__expf(le-m):0.f;
#pragma unroll
            for(int o=16;o;o>>=1) w+=__shfl_xor_sync(0xffffffffu,w,o);
            den+=w;
        }
        float inv=1.f/den;
        int e=e0;
        for(;e+3<e1;e+=4){
            int s0=sa[e],s1=sa[e+1],s2=sa[e+2],s3=sa[e+3];
            float4 x0=((const float4*)xa)[(size_t)s0*32+lane];
            float4 x1=((const float4*)xa)[(size_t)s1*32+lane];
            float4 x2=((const float4*)xa)[(size_t)s2*32+lane];
            float4 x3=((const float4*)xa)[(size_t)s3*32+lane];
            float a0=__expf(lg[e]-m)*inv,a1=__expf(lg[e+1]-m)*inv;
            float a2=__expf(lg[e+2]-m)*inv,a3=__expf(lg[e+3]-m)*inv;
            acc.x+=a0*x0.x+a1*x1.x+a2*x2.x+a3*x3.x;
            acc.y+=a0*x0.y+a1*x1.y+a2*x2.y+a3*x3.y;
            acc.z+=a0*x0.z+a1*x1.z+a2*x2.z+a3*x3.z;
            acc.w+=a0*x0.w+a1*x1.w+a2*x2.w+a3*x3.w;
        }
        for(;e<e1;e++){
            float a0=__expf(lg[e]-m)*inv;
            float4 x0=((const float4*)xa)[(size_t)sa[e]*32+lane];
            acc.x+=a0*x0.x; acc.y+=a0*x0.y; acc.z+=a0*x0.z; acc.w+=a0*x0.w;
        }
    }
    ((float4*)accap)[(size_t)dst*32+lane]=acc;

    float4 attv=((const float4*)attp)[lane];
    float4 bsv=((const float4*)bsp)[lane];
    float4 xrv=((const float4*)xrpp)[(size_t)dst*32+lane];
    float m=-INFINITY,den=0.f;
    float4 pa=make_float4(0.f,0.f,0.f,0.f);
    int p0=op[dst],p1=op[dst+1];
    for(int eb=p0;eb<p1;eb+=4){
        int g=min(4,p1-eb);
        int sl=(lane<g)?sp[eb+lane]:0;
        float4 xv[4];
        float lgv[4];
#pragma unroll
        for(int i=0;i<4;i++){
            if(i<g){
                int row=__shfl_sync(0xffffffffu,sl,i);
                xv[i]=((const float4*)xlpp)[(size_t)row*32+lane];
            }
        }
#pragma unroll
        for(int i=0;i<4;i++){
            if(i<g){
                float p=lrelu(xv[i].x+xrv.x)*attv.x+lrelu(xv[i].y+xrv.y)*attv.y
                       +lrelu(xv[i].z+xrv.z)*attv.z+lrelu(xv[i].w+xrv.w)*attv.w;
#pragma unroll
                for(int o=16;o;o>>=1) p+=__shfl_xor_sync(0xffffffffu,p,o);
                lgv[i]=p;
            }
        }
        float gm=m;
#pragma unroll
        for(int i=0;i<4;i++) if(i<g) gm=fmaxf(gm,lgv[i]);
        float sc=__expf(m-gm);
        den*=sc; pa.x*=sc; pa.y*=sc; pa.z*=sc; pa.w*=sc;
#pragma unroll
        for(int i=0;i<4;i++){
            if(i<g){
                float w=__expf(lgv[i]-gm);
                den+=w;
                pa.x+=w*xv[i].x; pa.y+=w*xv[i].y; pa.z+=w*xv[i].z; pa.w+=w*xv[i].w;
            }
        }
        m=gm;
    }
    float inv2=(den>0.f)?1.f/den:0.f;
    pa.x=pa.x*inv2+bsv.x; pa.y=pa.y*inv2+bsv.y; pa.z=pa.z*inv2+bsv.z; pa.w=pa.w*inv2+bsv.w;
    ((float4*)ppo)[(size_t)dst*32+lane]=pa;
}

__global__ void __launch_bounds__(256) k_final(
    const float* __restrict__ hid,const float* __restrict__ Wl,
    const float* __restrict__ bl,float* __restrict__ out){
    extern __shared__ char sm[];
    float* Ws=(float*)sm;
    float* hs=(float*)sm+D*DOUT;
    int t=threadIdx.x,lane=t&31,warp=t>>5;
    for(int i=t;i<D*DOUT/4;i+=256) ((float4*)Ws)[i]=((const float4*)Wl)[i];
    int row0=blockIdx.x*32+warp*4;
#pragma unroll
    for(int r=0;r<4;r++){
        float4 h=((const float4*)hid)[(size_t)(row0+r)*32+lane];
        h.x=fmaxf(h.x,0.f); h.y=fmaxf(h.y,0.f); h.z=fmaxf(h.z,0.f); h.w=fmaxf(h.w,0.f);
        ((float4*)&hs[(warp*4+r)*D])[lane]=h;
    }
    __syncthreads();
    float b0=bl[lane],b1=bl[lane+32];
    float a0[4],a1[4];
#pragma unroll
    for(int r=0;r<4;r++){ a0[r]=b0; a1[r]=b1; }
    for(int k=0;k<D;k++){
        float w0=Ws[k*DOUT+lane],w1=Ws[k*DOUT+lane+32];
#pragma unroll
        for(int r=0;r<4;r++){
            float h=hs[(warp*4+r)*D+k];
            a0[r]+=h*w0; a1[r]+=h*w1;
        }
    }
#pragma unroll
    for(int r=0;r<4;r++){
        int row=row0+r;
        out[(size_t)row*DOUT+lane]=a0[r];
        out[(size_t)row*DOUT+lane+32]=a1[r];
    }
}

extern "C" void kernel_launch(void* const* d_in,const int* in_sizes,int n_in,
                              void* d_out,int out_size){
    const float* xa=(const float*)d_in[0];
    const float* xp=(const float*)d_in[1];
    const int* ea=(const int*)d_in[2];
    const int* ep=(const int*)d_in[3];
    const float* Wla=(const float*)d_in[5];
    const float* bla=(const float*)d_in[6];
    const float* Wra=(const float*)d_in[7];
    const float* bra=(const float*)d_in[8];
    const float* ata=(const float*)d_in[9];
    const float* bsa=(const float*)d_in[10];
    const float* Wlp=(const float*)d_in[11];
    const float* blp=(const float*)d_in[12];
    const float* Wrp=(const float*)d_in[13];
    const float* brp=(const float*)d_in[14];
    const float* atp=(const float*)d_in[15];
    const float* bsp=(const float*)d_in[16];
    const float* Wf=(const float*)d_in[17];
    const float* bf=(const float*)d_in[18];
    float* out=(float*)d_out;
    int Ea=in_sizes[2]/2,Ep=in_sizes[3]/2,Eb=Ea+Ep;

    void* p;
    cudaGetSymbolAddress(&p,g_xlpp); float* xlpp=(float*)p;
    cudaGetSymbolAddress(&p,g_xrpp); float* xrpp=(float*)p;
    cudaGetSymbolAddress(&p,g_xrap); float* xrap=(float*)p;
    cudaGetSymbolAddress(&p,g_hid);  float* hid=(float*)p;
    cudaGetSymbolAddress(&p,g_acc);  float* accap=(float*)p;
    cudaGetSymbolAddress(&p,g_ppo);  float* ppo=(float*)p;
    cudaGetSymbolAddress(&p,g_lg);   float* lg=(float*)p;
    cudaGetSymbolAddress(&p,g_Bfh);  u64* Bfh=(u64*)p;
    cudaGetSymbolAddress(&p,g_Bfl);  u64* Bfl=(u64*)p;
    cudaGetSymbolAddress(&p,g_ca);   int* ca=(int*)p;
    cudaGetSymbolAddress(&p,g_cp);   int* cp=(int*)p;
    cudaGetSymbolAddress(&p,g_oa);   int* oa=(int*)p;
    cudaGetSymbolAddress(&p,g_op);   int* op=(int*)p;
    cudaGetSymbolAddress(&p,g_ua);   int* ua=(int*)p;
    cudaGetSymbolAddress(&p,g_up);   int* up=(int*)p;
    cudaGetSymbolAddress(&p,g_sa);   int* sa=(int*)p;
    cudaGetSymbolAddress(&p,g_da);   int* da=(int*)p;
    cudaGetSymbolAddress(&p,g_sp);   int* sp=(int*)p;

    cudaFuncSetAttribute(k_emma,cudaFuncAttributeMaxDynamicSharedMemorySize,135168);
    cudaFuncSetAttribute(k_final,cudaFuncAttributeMaxDynamicSharedMemorySize,49152);

    k_zero<<<(2*B+4096+255)/256,256>>>(ca,cp,Wla,Bfh,Bfl);
    k_hist<<<(Eb+255)/256,256>>>(ea,Ea,ca,ep,Ep,cp);
    k_scan<<<2,1024>>>(ca,oa,ua,cp,op,up);
    k_scat<<<(Eb+255)/256,256>>>(ea,Ea,ua,sa,da,ep,Ep,up,sp);
    k_gemm<0><<<B/128,256>>>(xp,Wra,bra,nullptr,xrap,B,nullptr);
    k_emma<<<(EA+127)/128,256,135168>>>(xa,Bfh,Bfl,bla,sa,&oa[B],da,xrap,ata,lg);
    k_gemm<0><<<(NP+127)/128,256>>>(xp,Wlp,blp,nullptr,xlpp,NP,nullptr);
    k_gemm<0><<<B/128,256>>>(xp,Wrp,brp,nullptr,xrpp,B,nullptr);
    k_agg<<<B/8,256>>>(xa,lg,oa,sa,xlpp,xrpp,atp,bsp,op,sp,accap,ppo);
    k_gemm<2><<<B/128,256>>>(accap,Wla,bla,bsa,hid,B,ppo);
    k_final<<<B/32,256,49152>>>(hid,Wf,bf,out);
}